// round 13
// baseline (speedup 1.0000x reference)
#include <cuda_runtime.h>

#define NF 8
#define NK 16
#define BB 32
#define YY 32
#define XX 32
#define PP 16
#define TT 8

__device__ float g_ky[NF*NK*YY];
__device__ float g_kx[NF*NK*XX];
__device__ float g_kp[NF*NK*PP];
__device__ float g_kt[NF*NK*TT];
__device__ float4 g_qmean4[YY*XX*PP*TT/4];
__device__ float g_integral[NF*NK];

// ---- packed f32x2 helpers (Blackwell FFMA2) ----
__device__ __forceinline__ float2 ffma2(float2 a, float2 b, float2 c) {
    float2 d;
    asm("{\n\t"
        ".reg .b64 ra, rb, rc, rd;\n\t"
        "mov.b64 ra, {%2, %3};\n\t"
        "mov.b64 rb, {%4, %5};\n\t"
        "mov.b64 rc, {%6, %7};\n\t"
        "fma.rn.f32x2 rd, ra, rb, rc;\n\t"
        "mov.b64 {%0, %1}, rd;\n\t"
        "}"
        : "=f"(d.x), "=f"(d.y)
        : "f"(a.x), "f"(a.y), "f"(b.x), "f"(b.y), "f"(c.x), "f"(c.y));
    return d;
}
__device__ __forceinline__ float2 fmul2(float2 a, float2 b) {
    float2 d;
    asm("{\n\t"
        ".reg .b64 ra, rb, rd;\n\t"
        "mov.b64 ra, {%2, %3};\n\t"
        "mov.b64 rb, {%4, %5};\n\t"
        "mul.rn.f32x2 rd, ra, rb;\n\t"
        "mov.b64 {%0, %1}, rd;\n\t"
        "}"
        : "=f"(d.x), "=f"(d.y)
        : "f"(a.x), "f"(a.y), "f"(b.x), "f"(b.y));
    return d;
}

// ---- Kernel 1: blocks 0..511 = qmean; blocks 512..519 = tables (spread) ----
__global__ __launch_bounds__(256, 4)
void prep_kernel(const float* __restrict__ quad,
                 const float* __restrict__ mean_lat, const float* __restrict__ logstd_lat,
                 const float* __restrict__ mean_lon, const float* __restrict__ logstd_lon,
                 const float* __restrict__ mean_lev, const float* __restrict__ logstd_lev,
                 const float* __restrict__ logtau,   float* __restrict__ out) {
    __shared__ float4 sdata[256];
    const int tid = threadIdx.x;
    const int bx  = blockIdx.x;

    if (bx < 512) {
        const int el = tid & 63;
        const int g  = tid >> 6;                     // 0..3
        const int e  = bx * 64 + el;                 // 512*64 = 32768 float4s
        const float4* q4 = reinterpret_cast<const float4*>(quad);
        float4 v[8];
        #pragma unroll
        for (int bb = 0; bb < 8; ++bb)
            v[bb] = q4[(size_t)(g * 8 + bb) * 32768 + e];
        float sx = 0.0f, sy = 0.0f, sz = 0.0f, sw = 0.0f;
        #pragma unroll
        for (int bb = 0; bb < 8; ++bb) {
            sx += v[bb].x; sy += v[bb].y; sz += v[bb].z; sw += v[bb].w;
        }
        sdata[tid] = make_float4(sx, sy, sz, sw);
        __syncthreads();
        if (g == 0) {
            float4 a = sdata[tid + 64];
            float4 c = sdata[tid + 128];
            float4 d = sdata[tid + 192];
            const float inv = 1.0f / (float)BB;
            g_qmean4[e] = make_float4((sx + a.x + c.x + d.x) * inv,
                                      (sy + a.y + c.y + d.y) * inv,
                                      (sz + a.z + c.z + d.z) * inv,
                                      (sw + a.w + c.w + d.w) * inv);
        }
    } else if (bx < 514) {
        const int base = (bx - 512) * 2048 + tid * 8;
        const int fk = base >> 5;
        const float m = mean_lat[fk];
        const float inv_s = expf(-logstd_lat[fk]);
        #pragma unroll
        for (int e = 0; e < 8; ++e) {
            int k = (base + e) & 31;
            float c = -1.0f + 2.0f * (float)k / (float)(YY - 1);
            float z = (c - m) * inv_s;
            g_ky[base + e] = expf(-0.5f * z * z);
        }
    } else if (bx < 516) {
        const int base = (bx - 514) * 2048 + tid * 8;
        const int fk = base >> 5;
        const float m = mean_lon[fk];
        const float inv_s = expf(-logstd_lon[fk]);
        #pragma unroll
        for (int e = 0; e < 8; ++e) {
            int k = (base + e) & 31;
            float c = -1.0f + 2.0f * (float)k / (float)(XX - 1);
            float z = (c - m) * inv_s;
            g_kx[base + e] = expf(-0.5f * z * z);
        }
    } else if (bx < 518) {
        const int base = (bx - 516) * 1024 + tid * 4;
        const int fk = base >> 4;
        const float m = mean_lev[fk];
        const float inv_s = expf(-logstd_lev[fk]);
        #pragma unroll
        for (int e = 0; e < 4; ++e) {
            int k = (base + e) & 15;
            float c = -1.0f + 2.0f * (float)k / (float)(PP - 1);
            float z = (c - m) * inv_s;
            g_kp[base + e] = expf(-0.5f * z * z);
        }
    } else if (bx == 518) {
        const int base = tid * 4;
        const int fk = base >> 3;
        const float inv_tau = 1.0f / (expf(logtau[fk]) + 1e-4f);
        #pragma unroll
        for (int e = 0; e < 4; ++e) {
            int t = (base + e) & 7;
            g_kt[base + e] = expf(-(float)t * inv_tau);
        }
    } else {
        float4* o4 = reinterpret_cast<float4*>(out);
        #pragma unroll
        for (int j = 0; j < 4; ++j)
            o4[tid + 256 * j] = make_float4(0.f, 0.f, 0.f, 0.f);
        if (tid < 128) g_integral[tid] = 0.0f;
    }
}

// ---- Kernel 2: main fused pass + integral side-job ----
// grid = 1024 = (b:32) x (ychunk:16, 2 y each) x (fhalf:2)
// 256 threads = 8 warps = (f_local:4) x (x-half:2). Lane owns (p, t-quad).
// Both quad rows + both ky*kx tables staged up front -> barrier-free mainloop.
// Horner over t in-loop (r = kt[1]); kp*kt[t0] deferred to epilogue.
// 3 blocks/SM: the deferred-weight loop is ~75 live regs -> fits the 84 cap.
__global__ __launch_bounds__(256, 3)
void feat_kernel(const float* __restrict__ field, const float* __restrict__ quad,
                 float* __restrict__ out) {
    __shared__ float4 sq4[2][1024];          // 32KB: both quad rows
    __shared__ float2 s_cf[2][1024];         // 16KB: ky*kx per (y, f_local, k-pair, x)

    const int tid  = threadIdx.x;
    const int lane = tid & 31;
    const int wid  = tid >> 5;
    const int f_local = wid >> 1;
    const int xh   = wid & 1;                // x-half this warp owns
    const int bx   = blockIdx.x;
    const int b    = bx >> 5;
    const int ych  = (bx >> 1) & 15;
    const int fh   = bx & 1;
    const int f    = fh * 4 + f_local;
    const int p    = lane >> 1;
    const int t0   = (lane & 1) * 4;

    // ---- integral side-job: stage qmean cell into (to-be-overwritten) cf smem ----
    if (tid < 32)
        reinterpret_cast<float4*>(&s_cf[0][0])[tid] = g_qmean4[bx * 32 + tid];

    // per-lane packed Horner ratios for ALL 8 k-pairs of this f (weights deferred)
    float2 r2[8];
    #pragma unroll
    for (int m = 0; m < 8; ++m) {
        int row0 = f * NK + 2 * m, row1 = row0 + 1;
        r2[m].x = g_kt[row0 * TT + 1];
        r2[m].y = g_kt[row1 * TT + 1];
    }
    __syncthreads();

    // integral contraction into a register (smem freed for cf afterwards)
    float s_int = 0.0f;
    if (tid < 128) {
        const float* iq = reinterpret_cast<const float*>(&s_cf[0][0]);
        const float* kt = &g_kt[tid * TT];
        const float* kp = &g_kp[tid * PP];
        #pragma unroll
        for (int pp = 0; pp < PP; ++pp) {
            float st = 0.0f;
            #pragma unroll
            for (int t = 0; t < TT; ++t)
                st += kt[t] * iq[pp * TT + t];
            s_int += kp[pp] * st;
        }
        int yc = bx >> 5, xc = bx & 31;
        s_int *= g_ky[tid * YY + yc] * g_kx[tid * XX + xc];
    }
    __syncthreads();

    // ---- stage BOTH quad rows + build BOTH cf tables ----
    const int y0 = ych * 2;
    #pragma unroll
    for (int yy = 0; yy < 2; ++yy) {
        const float4* qrow = reinterpret_cast<const float4*>(
            quad + (size_t)(b * YY + y0 + yy) * 4096);
        #pragma unroll
        for (int i = 0; i < 4; ++i)
            sq4[yy][tid + 256 * i] = qrow[tid + 256 * i];
        #pragma unroll
        for (int e = 0; e < 4; ++e) {
            int idx = tid * 4 + e;
            int fl = idx >> 8;
            int kp_i = (idx >> 5) & 7;
            int x = idx & 31;
            int fg = fh * 4 + fl;
            int k0 = 2 * kp_i;
            s_cf[yy][idx] = make_float2(
                g_ky[(fg * NK + k0) * YY + y0 + yy] * g_kx[(fg * NK + k0) * XX + x],
                g_ky[(fg * NK + k0 + 1) * YY + y0 + yy] * g_kx[(fg * NK + k0 + 1) * XX + x]);
        }
    }
    __syncthreads();

    // integral atomic (value safe in register)
    if (tid < 128)
        atomicAdd(&g_integral[tid], s_int);

    float2 acc[8];
    #pragma unroll
    for (int m = 0; m < 8; ++m) acc[m] = make_float2(0.0f, 0.0f);

    const int x0 = xh * 16;

    // ---- barrier-free mainloop over 2y x 16x ----
    #pragma unroll
    for (int yy = 0; yy < 2; ++yy) {
        const float4* frow = reinterpret_cast<const float4*>(
            field + (size_t)((b * NF + f) * YY + y0 + yy) * 4096);
        const float2* cf = &s_cf[yy][f_local * 256];
        const float4* sq = &sq4[yy][0];

        #pragma unroll 2
        for (int xi = 0; xi < 16; ++xi) {
            int x = x0 + xi;
            float4 fv = frow[x * 32 + lane];   // contiguous 512B per warp-instr
            float4 qv = sq[x * 32 + lane];     // conflict-free LDS.128
            float g0 = fv.x * qv.x;
            float g1 = fv.y * qv.y;
            float g2 = fv.z * qv.z;
            float g3 = fv.w * qv.w;
            float2 gg0 = make_float2(g0, g0);
            float2 gg1 = make_float2(g1, g1);
            float2 gg2 = make_float2(g2, g2);
            float2 gg3 = make_float2(g3, g3);
            #pragma unroll
            for (int m = 0; m < 8; ++m) {
                // Horner over t: ((g3*r + g2)*r + g1)*r + g0; weight deferred
                float2 s = ffma2(gg3, r2[m], gg2);
                s = ffma2(s, r2[m], gg1);
                s = ffma2(s, r2[m], gg0);
                acc[m] = ffma2(s, cf[m * 32 + x], acc[m]);
            }
        }
    }

    // ---- epilogue: apply deferred kp*kt[t0] weight, reduce, atomics ----
    #pragma unroll
    for (int m = 0; m < 8; ++m) {
        int row0 = f * NK + 2 * m, row1 = row0 + 1;
        float2 w0;
        w0.x = g_kp[row0 * PP + p] * g_kt[row0 * TT + t0];
        w0.y = g_kp[row1 * PP + p] * g_kt[row1 * TT + t0];
        float2 s = fmul2(acc[m], w0);
        float sx = s.x, sy = s.y;
        #pragma unroll
        for (int off = 16; off > 0; off >>= 1) {
            sx += __shfl_down_sync(0xffffffffu, sx, off);
            sy += __shfl_down_sync(0xffffffffu, sy, off);
        }
        if (lane == 0) {
            int kbase = b * (NF * NK) + f * NK + 2 * m;
            atomicAdd(&out[kbase],     sx);
            atomicAdd(&out[kbase + 1], sy);
        }
    }
}

// ---- Kernel 3: normalize by integral ----
__global__ void norm_kernel(float* __restrict__ out) {
    int i = blockIdx.x * 256 + threadIdx.x;   // 4096
    out[i] = out[i] / (g_integral[i & 127] + 1e-4f);
}

extern "C" void kernel_launch(void* const* d_in, const int* in_sizes, int n_in,
                              void* d_out, int out_size) {
    const float* field      = (const float*)d_in[0];
    const float* quad       = (const float*)d_in[1];
    const float* mean_lat   = (const float*)d_in[2];
    const float* logstd_lat = (const float*)d_in[3];
    const float* mean_lon   = (const float*)d_in[4];
    const float* logstd_lon = (const float*)d_in[5];
    const float* mean_lev   = (const float*)d_in[6];
    const float* logstd_lev = (const float*)d_in[7];
    const float* logtau     = (const float*)d_in[8];
    float* out = (float*)d_out;

    prep_kernel<<<520, 256>>>(quad, mean_lat, logstd_lat, mean_lon, logstd_lon,
                              mean_lev, logstd_lev, logtau, out);
    feat_kernel<<<1024, 256>>>(field, quad, out);
    norm_kernel<<<16, 256>>>(out);
}

// round 14
// speedup vs baseline: 1.1047x; 1.1047x over previous
#include <cuda_runtime.h>

#define NF 8
#define NK 16
#define BB 32
#define YY 32
#define XX 32
#define PP 16
#define TT 8

__device__ float g_ky[NF*NK*YY];
__device__ float g_kx[NF*NK*XX];
__device__ float g_kp[NF*NK*PP];
__device__ float g_kt[NF*NK*TT];
__device__ float4 g_qmean4[YY*XX*PP*TT/4];
__device__ float g_integral[NF*NK];

// ---- packed f32x2 helpers (Blackwell FFMA2) ----
__device__ __forceinline__ float2 ffma2(float2 a, float2 b, float2 c) {
    float2 d;
    asm("{\n\t"
        ".reg .b64 ra, rb, rc, rd;\n\t"
        "mov.b64 ra, {%2, %3};\n\t"
        "mov.b64 rb, {%4, %5};\n\t"
        "mov.b64 rc, {%6, %7};\n\t"
        "fma.rn.f32x2 rd, ra, rb, rc;\n\t"
        "mov.b64 {%0, %1}, rd;\n\t"
        "}"
        : "=f"(d.x), "=f"(d.y)
        : "f"(a.x), "f"(a.y), "f"(b.x), "f"(b.y), "f"(c.x), "f"(c.y));
    return d;
}
__device__ __forceinline__ float2 fmul2(float2 a, float2 b) {
    float2 d;
    asm("{\n\t"
        ".reg .b64 ra, rb, rd;\n\t"
        "mov.b64 ra, {%2, %3};\n\t"
        "mov.b64 rb, {%4, %5};\n\t"
        "mul.rn.f32x2 rd, ra, rb;\n\t"
        "mov.b64 {%0, %1}, rd;\n\t"
        "}"
        : "=f"(d.x), "=f"(d.y)
        : "f"(a.x), "f"(a.y), "f"(b.x), "f"(b.y));
    return d;
}

// ---- Kernel 1: blocks 0..511 = qmean; blocks 512..519 = tables (spread) ----
__global__ __launch_bounds__(256, 4)
void prep_kernel(const float* __restrict__ quad,
                 const float* __restrict__ mean_lat, const float* __restrict__ logstd_lat,
                 const float* __restrict__ mean_lon, const float* __restrict__ logstd_lon,
                 const float* __restrict__ mean_lev, const float* __restrict__ logstd_lev,
                 const float* __restrict__ logtau,   float* __restrict__ out) {
    __shared__ float4 sdata[256];
    const int tid = threadIdx.x;
    const int bx  = blockIdx.x;

    if (bx < 512) {
        const int el = tid & 63;
        const int g  = tid >> 6;                     // 0..3
        const int e  = bx * 64 + el;                 // 512*64 = 32768 float4s
        const float4* q4 = reinterpret_cast<const float4*>(quad);
        float4 v[8];
        #pragma unroll
        for (int bb = 0; bb < 8; ++bb)
            v[bb] = q4[(size_t)(g * 8 + bb) * 32768 + e];
        float sx = 0.0f, sy = 0.0f, sz = 0.0f, sw = 0.0f;
        #pragma unroll
        for (int bb = 0; bb < 8; ++bb) {
            sx += v[bb].x; sy += v[bb].y; sz += v[bb].z; sw += v[bb].w;
        }
        sdata[tid] = make_float4(sx, sy, sz, sw);
        __syncthreads();
        if (g == 0) {
            float4 a = sdata[tid + 64];
            float4 c = sdata[tid + 128];
            float4 d = sdata[tid + 192];
            const float inv = 1.0f / (float)BB;
            g_qmean4[e] = make_float4((sx + a.x + c.x + d.x) * inv,
                                      (sy + a.y + c.y + d.y) * inv,
                                      (sz + a.z + c.z + d.z) * inv,
                                      (sw + a.w + c.w + d.w) * inv);
        }
    } else if (bx < 514) {
        const int base = (bx - 512) * 2048 + tid * 8;
        const int fk = base >> 5;
        const float m = mean_lat[fk];
        const float inv_s = expf(-logstd_lat[fk]);
        #pragma unroll
        for (int e = 0; e < 8; ++e) {
            int k = (base + e) & 31;
            float c = -1.0f + 2.0f * (float)k / (float)(YY - 1);
            float z = (c - m) * inv_s;
            g_ky[base + e] = expf(-0.5f * z * z);
        }
    } else if (bx < 516) {
        const int base = (bx - 514) * 2048 + tid * 8;
        const int fk = base >> 5;
        const float m = mean_lon[fk];
        const float inv_s = expf(-logstd_lon[fk]);
        #pragma unroll
        for (int e = 0; e < 8; ++e) {
            int k = (base + e) & 31;
            float c = -1.0f + 2.0f * (float)k / (float)(XX - 1);
            float z = (c - m) * inv_s;
            g_kx[base + e] = expf(-0.5f * z * z);
        }
    } else if (bx < 518) {
        const int base = (bx - 516) * 1024 + tid * 4;
        const int fk = base >> 4;
        const float m = mean_lev[fk];
        const float inv_s = expf(-logstd_lev[fk]);
        #pragma unroll
        for (int e = 0; e < 4; ++e) {
            int k = (base + e) & 15;
            float c = -1.0f + 2.0f * (float)k / (float)(PP - 1);
            float z = (c - m) * inv_s;
            g_kp[base + e] = expf(-0.5f * z * z);
        }
    } else if (bx == 518) {
        const int base = tid * 4;
        const int fk = base >> 3;
        const float inv_tau = 1.0f / (expf(logtau[fk]) + 1e-4f);
        #pragma unroll
        for (int e = 0; e < 4; ++e) {
            int t = (base + e) & 7;
            g_kt[base + e] = expf(-(float)t * inv_tau);
        }
    } else {
        float4* o4 = reinterpret_cast<float4*>(out);
        #pragma unroll
        for (int j = 0; j < 4; ++j)
            o4[tid + 256 * j] = make_float4(0.f, 0.f, 0.f, 0.f);
        if (tid < 128) g_integral[tid] = 0.0f;
    }
}

// ---- Kernel 2: main fused pass + integral side-job ----
// grid = 1024 = (b:32) x (ychunk:16, 2 y each) x (fhalf:2)
// 256 threads = 8 warps = (f_local:4) x (x-half:2). Lane owns (p, t-quad).
// Mainloop flattened to 32 iters with a 4-deep register prefetch ring for the
// field loads: iteration xi consumes the LDG issued at xi-4 -> DRAM latency
// fully covered by ~4 iterations of compute. kp*kt[t0] deferred to epilogue.
__global__ __launch_bounds__(256, 2)
void feat_kernel(const float* __restrict__ field, const float* __restrict__ quad,
                 float* __restrict__ out) {
    __shared__ float4 sq4[2048];             // 32KB: both quad rows (flat)
    __shared__ float2 s_cf[2][1024];         // 16KB: ky*kx per (y, f_local, k-pair, x)

    const int tid  = threadIdx.x;
    const int lane = tid & 31;
    const int wid  = tid >> 5;
    const int f_local = wid >> 1;
    const int xh   = wid & 1;                // x-half this warp owns
    const int bx   = blockIdx.x;
    const int b    = bx >> 5;
    const int ych  = (bx >> 1) & 15;
    const int fh   = bx & 1;
    const int f    = fh * 4 + f_local;
    const int p    = lane >> 1;
    const int t0   = (lane & 1) * 4;

    // ---- integral side-job: stage qmean cell into (to-be-overwritten) cf smem ----
    if (tid < 32)
        reinterpret_cast<float4*>(&s_cf[0][0])[tid] = g_qmean4[bx * 32 + tid];

    // per-lane packed Horner ratios for ALL 8 k-pairs of this f (weights deferred)
    float2 r2[8];
    #pragma unroll
    for (int m = 0; m < 8; ++m) {
        int row0 = f * NK + 2 * m, row1 = row0 + 1;
        r2[m].x = g_kt[row0 * TT + 1];
        r2[m].y = g_kt[row1 * TT + 1];
    }
    __syncthreads();

    // integral contraction into a register (smem freed for cf afterwards)
    float s_int = 0.0f;
    if (tid < 128) {
        const float* iq = reinterpret_cast<const float*>(&s_cf[0][0]);
        const float* kt = &g_kt[tid * TT];
        const float* kp = &g_kp[tid * PP];
        #pragma unroll
        for (int pp = 0; pp < PP; ++pp) {
            float st = 0.0f;
            #pragma unroll
            for (int t = 0; t < TT; ++t)
                st += kt[t] * iq[pp * TT + t];
            s_int += kp[pp] * st;
        }
        int yc = bx >> 5, xc = bx & 31;
        s_int *= g_ky[tid * YY + yc] * g_kx[tid * XX + xc];
    }
    __syncthreads();

    // ---- stage BOTH quad rows + build BOTH cf tables ----
    const int y0 = ych * 2;
    #pragma unroll
    for (int yy = 0; yy < 2; ++yy) {
        const float4* qrow = reinterpret_cast<const float4*>(
            quad + (size_t)(b * YY + y0 + yy) * 4096);
        #pragma unroll
        for (int i = 0; i < 4; ++i)
            sq4[yy * 1024 + tid + 256 * i] = qrow[tid + 256 * i];
        #pragma unroll
        for (int e = 0; e < 4; ++e) {
            int idx = tid * 4 + e;
            int fl = idx >> 8;
            int kp_i = (idx >> 5) & 7;
            int x = idx & 31;
            int fg = fh * 4 + fl;
            int k0 = 2 * kp_i;
            s_cf[yy][idx] = make_float2(
                g_ky[(fg * NK + k0) * YY + y0 + yy] * g_kx[(fg * NK + k0) * XX + x],
                g_ky[(fg * NK + k0 + 1) * YY + y0 + yy] * g_kx[(fg * NK + k0 + 1) * XX + x]);
        }
    }
    __syncthreads();

    // integral atomic (value safe in register)
    if (tid < 128)
        atomicAdd(&g_integral[tid], s_int);

    float2 acc[8];
    #pragma unroll
    for (int m = 0; m < 8; ++m) acc[m] = make_float2(0.0f, 0.0f);

    const int x0 = xh * 16;
    // Both field rows (y0, y0+1) are contiguous: one base pointer, linear index.
    const float4* frow2 = reinterpret_cast<const float4*>(
        field + (size_t)((b * NF + f) * YY + y0) * 4096);

    // float4 index for flattened iteration xi (0..31): yy = xi>>4, x = x0+(xi&15)
    #define LIN(xi) ((((xi) >> 4) * 32 + x0 + ((xi) & 15)) * 32 + lane)

    // ---- software-pipelined mainloop: 4-deep field prefetch ring ----
    float4 fbuf[4];
    #pragma unroll
    for (int i = 0; i < 4; ++i)
        fbuf[i] = frow2[LIN(i)];

    #pragma unroll 4
    for (int xi = 0; xi < 32; ++xi) {
        float4 fv = fbuf[xi & 3];
        int nxt = xi + 4;
        if (nxt < 32)
            fbuf[xi & 3] = frow2[LIN(nxt)];    // issued now, consumed 4 iters later
        float4 qv = sq4[LIN(xi)];              // conflict-free LDS.128
        const float2* cf = &s_cf[xi >> 4][f_local * 256 + (x0 + (xi & 15))];
        float g0 = fv.x * qv.x;
        float g1 = fv.y * qv.y;
        float g2 = fv.z * qv.z;
        float g3 = fv.w * qv.w;
        float2 gg0 = make_float2(g0, g0);
        float2 gg1 = make_float2(g1, g1);
        float2 gg2 = make_float2(g2, g2);
        float2 gg3 = make_float2(g3, g3);
        #pragma unroll
        for (int m = 0; m < 8; ++m) {
            // Horner over t: ((g3*r + g2)*r + g1)*r + g0; weight deferred
            float2 s = ffma2(gg3, r2[m], gg2);
            s = ffma2(s, r2[m], gg1);
            s = ffma2(s, r2[m], gg0);
            acc[m] = ffma2(s, cf[m * 32], acc[m]);
        }
    }
    #undef LIN

    // ---- epilogue: apply deferred kp*kt[t0] weight, reduce, atomics ----
    #pragma unroll
    for (int m = 0; m < 8; ++m) {
        int row0 = f * NK + 2 * m, row1 = row0 + 1;
        float2 w0;
        w0.x = g_kp[row0 * PP + p] * g_kt[row0 * TT + t0];
        w0.y = g_kp[row1 * PP + p] * g_kt[row1 * TT + t0];
        float2 s = fmul2(acc[m], w0);
        float sx = s.x, sy = s.y;
        #pragma unroll
        for (int off = 16; off > 0; off >>= 1) {
            sx += __shfl_down_sync(0xffffffffu, sx, off);
            sy += __shfl_down_sync(0xffffffffu, sy, off);
        }
        if (lane == 0) {
            int kbase = b * (NF * NK) + f * NK + 2 * m;
            atomicAdd(&out[kbase],     sx);
            atomicAdd(&out[kbase + 1], sy);
        }
    }
}

// ---- Kernel 3: normalize by integral ----
__global__ void norm_kernel(float* __restrict__ out) {
    int i = blockIdx.x * 256 + threadIdx.x;   // 4096
    out[i] = out[i] / (g_integral[i & 127] + 1e-4f);
}

extern "C" void kernel_launch(void* const* d_in, const int* in_sizes, int n_in,
                              void* d_out, int out_size) {
    const float* field      = (const float*)d_in[0];
    const float* quad       = (const float*)d_in[1];
    const float* mean_lat   = (const float*)d_in[2];
    const float* logstd_lat = (const float*)d_in[3];
    const float* mean_lon   = (const float*)d_in[4];
    const float* logstd_lon = (const float*)d_in[5];
    const float* mean_lev   = (const float*)d_in[6];
    const float* logstd_lev = (const float*)d_in[7];
    const float* logtau     = (const float*)d_in[8];
    float* out = (float*)d_out;

    prep_kernel<<<520, 256>>>(quad, mean_lat, logstd_lat, mean_lon, logstd_lon,
                              mean_lev, logstd_lev, logtau, out);
    feat_kernel<<<1024, 256>>>(field, quad, out);
    norm_kernel<<<16, 256>>>(out);
}